// round 1
// baseline (speedup 1.0000x reference)
#include <cuda_runtime.h>

// ConvEmbedding: out[n,i] = normalize_row( sum_k w[i,k]*x[n,i+k] + b[i] )
// == C = X(16384x2048) @ W_band(512x2048)^T, band W_band[i, i+k] = w[i,k], k<1537.

#define N_ROWS 16384
#define D_DIM  2048
#define E_DIM  512
#define K_DIM  1537

// Scratch: dense banded weight matrix (4 MB), built once per launch.
__device__ float g_Wb[E_DIM * D_DIM];

// ---------------------------------------------------------------------------
// Kernel 1: scatter w (E,K) into dense banded W_band (E,D)
// ---------------------------------------------------------------------------
__global__ void build_band_kernel(const float* __restrict__ w) {
    const int i = blockIdx.x;                    // output row 0..511
    const float* wrow = w + (size_t)i * K_DIM;
    float* orow = g_Wb + (size_t)i * D_DIM;
    for (int c = threadIdx.x; c < D_DIM; c += blockDim.x) {
        const int k = c - i;
        orow[c] = (k >= 0 && k < K_DIM) ? wrow[k] : 0.0f;
    }
}

// ---------------------------------------------------------------------------
// Kernel 2: register-blocked fp32 SGEMM, band-aware K range.
//   C[n,e] = sum_k X[n,k] * Wb[e,k]
// Tiles: BM=128, BN=128, BK=8, per-thread 8x8, 256 threads.
// For column tile starting at i0, nonzero k range is [i0, i0+BN-1+K_DIM-1],
// i.e. exactly 1664 columns (multiple of BK) for every tile.
// ---------------------------------------------------------------------------
#define BM 128
#define BN 128
#define BK 8
#define TM 8
#define TN 8

__global__ __launch_bounds__(256, 2)
void gemm_band_kernel(const float* __restrict__ X, float* __restrict__ C) {
    __shared__ float As[BK][BM];   // X tile, transposed  (k, m)
    __shared__ float Bs[BK][BN];   // W tile, transposed  (k, e)

    const int bx = blockIdx.x;     // E tile index (0..3)
    const int by = blockIdx.y;     // N tile index (0..127)
    const int tid = threadIdx.x;

    const int tCol = tid % (BN / TN);   // 0..15
    const int tRow = tid / (BN / TN);   // 0..15

    const int i0     = bx * BN;
    const int kStart = i0;                                   // multiple of 8
    const int kEnd   = min(D_DIM, i0 + BN + K_DIM - 1);      // i0 + 1664 (or 2048)

    const float* Xp = X    + (size_t)by * BM * D_DIM;
    const float* Wp = g_Wb + (size_t)i0 * D_DIM;

    // loader mapping: each thread loads one float4 of A and one of B per k-tile
    const int lr = tid >> 1;           // row within tile 0..127
    const int lc = (tid & 1) * 4;      // col offset 0 or 4

    float acc[TM][TN];
    #pragma unroll
    for (int i = 0; i < TM; i++)
        #pragma unroll
        for (int j = 0; j < TN; j++) acc[i][j] = 0.0f;

    for (int k0 = kStart; k0 < kEnd; k0 += BK) {
        float4 av = *reinterpret_cast<const float4*>(Xp + (size_t)lr * D_DIM + k0 + lc);
        As[lc + 0][lr] = av.x;
        As[lc + 1][lr] = av.y;
        As[lc + 2][lr] = av.z;
        As[lc + 3][lr] = av.w;
        float4 bv = *reinterpret_cast<const float4*>(Wp + (size_t)lr * D_DIM + k0 + lc);
        Bs[lc + 0][lr] = bv.x;
        Bs[lc + 1][lr] = bv.y;
        Bs[lc + 2][lr] = bv.z;
        Bs[lc + 3][lr] = bv.w;
        __syncthreads();

        #pragma unroll
        for (int k = 0; k < BK; k++) {
            float regM[TM], regN[TN];
            // vectorized shared loads (two float4 each)
            float4 m0 = *reinterpret_cast<const float4*>(&As[k][tRow * TM]);
            float4 m1 = *reinterpret_cast<const float4*>(&As[k][tRow * TM + 4]);
            float4 n0 = *reinterpret_cast<const float4*>(&Bs[k][tCol * TN]);
            float4 n1 = *reinterpret_cast<const float4*>(&Bs[k][tCol * TN + 4]);
            regM[0]=m0.x; regM[1]=m0.y; regM[2]=m0.z; regM[3]=m0.w;
            regM[4]=m1.x; regM[5]=m1.y; regM[6]=m1.z; regM[7]=m1.w;
            regN[0]=n0.x; regN[1]=n0.y; regN[2]=n0.z; regN[3]=n0.w;
            regN[4]=n1.x; regN[5]=n1.y; regN[6]=n1.z; regN[7]=n1.w;
            #pragma unroll
            for (int i = 0; i < TM; i++)
                #pragma unroll
                for (int j = 0; j < TN; j++)
                    acc[i][j] = fmaf(regM[i], regN[j], acc[i][j]);
        }
        __syncthreads();
    }

    // store 8x8 per thread, vectorized
    #pragma unroll
    for (int i = 0; i < TM; i++) {
        float* Cp = C + (size_t)(by * BM + tRow * TM + i) * E_DIM + i0 + tCol * TN;
        *reinterpret_cast<float4*>(Cp)     = make_float4(acc[i][0], acc[i][1], acc[i][2], acc[i][3]);
        *reinterpret_cast<float4*>(Cp + 4) = make_float4(acc[i][4], acc[i][5], acc[i][6], acc[i][7]);
    }
}

// ---------------------------------------------------------------------------
// Kernel 3: add bias + L2-normalize each row of 512, in place.
// One block of 128 threads per row; 4 elems (one float4) per thread.
// ---------------------------------------------------------------------------
__global__ void bias_normalize_kernel(float* __restrict__ C, const float* __restrict__ b) {
    const int row = blockIdx.x;
    float* Cp = C + (size_t)row * E_DIM;
    const int t = threadIdx.x;  // 0..127

    float4 v  = reinterpret_cast<float4*>(Cp)[t];
    float4 bb = reinterpret_cast<const float4*>(b)[t];
    v.x += bb.x; v.y += bb.y; v.z += bb.z; v.w += bb.w;

    float ss = v.x * v.x + v.y * v.y + v.z * v.z + v.w * v.w;
    #pragma unroll
    for (int o = 16; o > 0; o >>= 1)
        ss += __shfl_xor_sync(0xffffffff, ss, o);

    __shared__ float warpsum[4];
    if ((t & 31) == 0) warpsum[t >> 5] = ss;
    __syncthreads();
    const float tot = warpsum[0] + warpsum[1] + warpsum[2] + warpsum[3];

    const float nrm   = sqrtf(tot);
    const float scale = 1.0f / fmaxf(nrm, 1e-12f);

    v.x *= scale; v.y *= scale; v.z *= scale; v.w *= scale;
    reinterpret_cast<float4*>(Cp)[t] = v;
}

// ---------------------------------------------------------------------------
extern "C" void kernel_launch(void* const* d_in, const int* in_sizes, int n_in,
                              void* d_out, int out_size) {
    const float* x = (const float*)d_in[0];   // (16384, 2048)
    const float* w = (const float*)d_in[1];   // (512, 1537)
    const float* b = (const float*)d_in[2];   // (512,)
    float* out = (float*)d_out;               // (16384, 512)

    build_band_kernel<<<E_DIM, 256>>>(w);

    dim3 grid(E_DIM / BN, N_ROWS / BM);       // (4, 128)
    gemm_band_kernel<<<grid, 256>>>(x, out);

    bias_normalize_kernel<<<N_ROWS, 128>>>(out, b);
}

// round 3
// speedup vs baseline: 2.6041x; 2.6041x over previous
#include <cuda_runtime.h>
#include <cuda_bf16.h>
#include <cstdint>

// ConvEmbedding: out[n,i] = normalize_row( sum_k w[i,k]*x[n,i+k] + b[i] )
// C = X(16384x2048) @ W_band(512x2048)^T, bf16 3-term split via mma.sync (HMMA).

#define N_ROWS 16384
#define D_DIM  2048
#define E_DIM  512
#define K_DIM  1537

#define BM 128
#define BN 128
#define BK 32
#define PITCH 40                 // bf16 elems per smem row (80 B)
#define NITER 52                 // 1664 / 32, uniform for every E tile
#define THREADS 256

#define TILE_SMEM (BM * PITCH * 2)           // 10240 B per tile
#define STAGE_SMEM (4 * TILE_SMEM)           // Ahi, Alo, Bhi, Blo = 40960 B
#define SMEM_BYTES (2 * STAGE_SMEM)          // double buffered = 81920 B

// ---------------- scratch (device globals) ----------------------------------
__device__ __nv_bfloat16 g_Xhi[(size_t)N_ROWS * D_DIM];
__device__ __nv_bfloat16 g_Xlo[(size_t)N_ROWS * D_DIM];
__device__ __nv_bfloat16 g_Whi[(size_t)E_DIM * D_DIM];
__device__ __nv_bfloat16 g_Wlo[(size_t)E_DIM * D_DIM];

// ---------------- kernel 1: split X into bf16 hi/lo --------------------------
__global__ __launch_bounds__(256)
void split_x_kernel(const float* __restrict__ x) {
    size_t i = ((size_t)blockIdx.x * 256 + threadIdx.x) * 8;
    float4 a = *reinterpret_cast<const float4*>(x + i);
    float4 c = *reinterpret_cast<const float4*>(x + i + 4);
    float v[8] = {a.x, a.y, a.z, a.w, c.x, c.y, c.z, c.w};
    __nv_bfloat16 hi[8], lo[8];
    #pragma unroll
    for (int j = 0; j < 8; j++) {
        hi[j] = __float2bfloat16(v[j]);
        lo[j] = __float2bfloat16(v[j] - __bfloat162float(hi[j]));
    }
    *reinterpret_cast<uint4*>(&g_Xhi[i]) = *reinterpret_cast<uint4*>(hi);
    *reinterpret_cast<uint4*>(&g_Xlo[i]) = *reinterpret_cast<uint4*>(lo);
}

// ---------------- kernel 2: build banded W, split hi/lo ----------------------
__global__ void build_band_kernel(const float* __restrict__ w) {
    const int i = blockIdx.x;  // 0..511
    const float* wrow = w + (size_t)i * K_DIM;
    for (int c = threadIdx.x; c < D_DIM; c += blockDim.x) {
        const int k = c - i;
        const float val = (k >= 0 && k < K_DIM) ? wrow[k] : 0.0f;
        const __nv_bfloat16 hi = __float2bfloat16(val);
        g_Whi[(size_t)i * D_DIM + c] = hi;
        g_Wlo[(size_t)i * D_DIM + c] = __float2bfloat16(val - __bfloat162float(hi));
    }
}

// ---------------- mma helpers ------------------------------------------------
__device__ __forceinline__ void ldm_x4(uint32_t* r, uint32_t saddr) {
    asm volatile("ldmatrix.sync.aligned.m8n8.x4.shared.b16 {%0,%1,%2,%3}, [%4];"
                 : "=r"(r[0]), "=r"(r[1]), "=r"(r[2]), "=r"(r[3]) : "r"(saddr));
}
__device__ __forceinline__ void mma_bf16(float* d, const uint32_t* a, const uint32_t* b) {
    asm volatile(
        "mma.sync.aligned.m16n8k16.row.col.f32.bf16.bf16.f32 "
        "{%0,%1,%2,%3}, {%4,%5,%6,%7}, {%8,%9}, {%0,%1,%2,%3};"
        : "+f"(d[0]), "+f"(d[1]), "+f"(d[2]), "+f"(d[3])
        : "r"(a[0]), "r"(a[1]), "r"(a[2]), "r"(a[3]), "r"(b[0]), "r"(b[1]));
}
__device__ __forceinline__ void cp_async16(uint32_t saddr, const void* gaddr) {
    asm volatile("cp.async.cg.shared.global [%0], [%1], 16;" :: "r"(saddr), "l"(gaddr));
}

// ---------------- kernel 3: bf16-split GEMM ----------------------------------
__global__ __launch_bounds__(THREADS, 2)
void mma_gemm_kernel(float* __restrict__ C) {
    extern __shared__ __align__(128) char smem[];
    const uint32_t sb = (uint32_t)__cvta_generic_to_shared(smem);

    const int tid  = threadIdx.x;
    const int lane = tid & 31;
    const int wid  = tid >> 5;
    const int wm   = wid & 3;          // 4 warps along M: rows wm*32
    const int wn   = wid >> 2;         // 2 warps along N: cols wn*64
    const int bx = blockIdx.x;         // E tile (0..3)
    const int by = blockIdx.y;         // batch tile (0..127)
    const int i0 = bx * BN;
    const int kStart = i0;

    // loader sources (tile order: 0=Ahi 1=Alo 2=Bhi 3=Blo)
    const __nv_bfloat16* srcs[4] = {
        g_Xhi + (size_t)by * BM * D_DIM,
        g_Xlo + (size_t)by * BM * D_DIM,
        g_Whi + (size_t)i0 * D_DIM,
        g_Wlo + (size_t)i0 * D_DIM
    };

    // per-thread loader coords: iteration i handles tile i>>1
    int lrow[8], lcol[8];
    #pragma unroll
    for (int i = 0; i < 8; i++) {
        const int v = ((i & 1) << 8) + tid;   // 0..511 within tile
        lrow[i] = v >> 2;
        lcol[i] = (v & 3) * 8;
    }

    // fragment smem offsets (bytes, lane-dependent), relative to tile base
    const uint32_t aoff = ((uint32_t)((wm * 32 + (lane & 15)) * PITCH + (lane >> 4) * 8)) * 2;
    const uint32_t boff = ((uint32_t)((wn * 64 + (lane >> 4) * 8 + (lane & 7)) * PITCH
                                      + ((lane >> 3) & 1) * 8)) * 2;

    float acc[2][8][4];
    #pragma unroll
    for (int mt = 0; mt < 2; mt++)
        #pragma unroll
        for (int nt = 0; nt < 8; nt++)
            #pragma unroll
            for (int q = 0; q < 4; q++) acc[mt][nt][q] = 0.0f;

    // ---- prologue: load stage 0
    {
        const int k0 = kStart;
        #pragma unroll
        for (int i = 0; i < 8; i++) {
            const int t = i >> 1;
            cp_async16(sb + t * TILE_SMEM + (lrow[i] * PITCH + lcol[i]) * 2,
                       srcs[t] + (size_t)lrow[i] * D_DIM + k0 + lcol[i]);
        }
        asm volatile("cp.async.commit_group;" ::: "memory");
    }

    for (int it = 0; it < NITER; it++) {
        if (it + 1 < NITER) {
            const int k0 = kStart + (it + 1) * BK;
            const uint32_t stg = sb + ((it + 1) & 1) * STAGE_SMEM;
            #pragma unroll
            for (int i = 0; i < 8; i++) {
                const int t = i >> 1;
                cp_async16(stg + t * TILE_SMEM + (lrow[i] * PITCH + lcol[i]) * 2,
                           srcs[t] + (size_t)lrow[i] * D_DIM + k0 + lcol[i]);
            }
            asm volatile("cp.async.commit_group;" ::: "memory");
            asm volatile("cp.async.wait_group 1;" ::: "memory");
        } else {
            asm volatile("cp.async.wait_group 0;" ::: "memory");
        }
        __syncthreads();

        const uint32_t stg = sb + (it & 1) * STAGE_SMEM;
        const uint32_t sAhi = stg + 0 * TILE_SMEM + aoff;
        const uint32_t sAlo = stg + 1 * TILE_SMEM + aoff;
        const uint32_t sBhi = stg + 2 * TILE_SMEM + boff;
        const uint32_t sBlo = stg + 3 * TILE_SMEM + boff;

        #pragma unroll
        for (int k16 = 0; k16 < BK; k16 += 16) {
            const uint32_t ko = k16 * 2;  // byte offset in row
            uint32_t a[8], b[16];

            // b_hi (4 x ldmatrix.x4 = 8 n8-tiles)
            #pragma unroll
            for (int bt = 0; bt < 4; bt++)
                ldm_x4(&b[bt * 4], sBhi + (uint32_t)(bt * 16 * PITCH) * 2 + ko);
            // a_hi (2 m16 tiles)
            #pragma unroll
            for (int mt = 0; mt < 2; mt++)
                ldm_x4(&a[mt * 4], sAhi + (uint32_t)(mt * 16 * PITCH) * 2 + ko);
            // term 1: a_hi * b_hi
            #pragma unroll
            for (int mt = 0; mt < 2; mt++)
                #pragma unroll
                for (int nt = 0; nt < 8; nt++)
                    mma_bf16(acc[mt][nt], &a[mt * 4], &b[nt * 2]);

            // term 3: a_lo * b_hi (b still resident)
            #pragma unroll
            for (int mt = 0; mt < 2; mt++)
                ldm_x4(&a[mt * 4], sAlo + (uint32_t)(mt * 16 * PITCH) * 2 + ko);
            #pragma unroll
            for (int mt = 0; mt < 2; mt++)
                #pragma unroll
                for (int nt = 0; nt < 8; nt++)
                    mma_bf16(acc[mt][nt], &a[mt * 4], &b[nt * 2]);

            // term 2: a_hi * b_lo
            #pragma unroll
            for (int bt = 0; bt < 4; bt++)
                ldm_x4(&b[bt * 4], sBlo + (uint32_t)(bt * 16 * PITCH) * 2 + ko);
            #pragma unroll
            for (int mt = 0; mt < 2; mt++)
                ldm_x4(&a[mt * 4], sAhi + (uint32_t)(mt * 16 * PITCH) * 2 + ko);
            #pragma unroll
            for (int mt = 0; mt < 2; mt++)
                #pragma unroll
                for (int nt = 0; nt < 8; nt++)
                    mma_bf16(acc[mt][nt], &a[mt * 4], &b[nt * 2]);
        }
        __syncthreads();
    }

    // ---- epilogue: direct stores, C frag layout of m16n8
    const int g = lane >> 2;
    const int c = lane & 3;
    #pragma unroll
    for (int mt = 0; mt < 2; mt++) {
        const int row0 = by * BM + wm * 32 + mt * 16 + g;
        #pragma unroll
        for (int nt = 0; nt < 8; nt++) {
            const int col = i0 + wn * 64 + nt * 8 + c * 2;
            float* p0 = C + (size_t)row0 * E_DIM + col;
            float* p1 = C + (size_t)(row0 + 8) * E_DIM + col;
            *reinterpret_cast<float2*>(p0) = make_float2(acc[mt][nt][0], acc[mt][nt][1]);
            *reinterpret_cast<float2*>(p1) = make_float2(acc[mt][nt][2], acc[mt][nt][3]);
        }
    }
}

// ---------------- kernel 4: bias + L2 normalize ------------------------------
__global__ void bias_normalize_kernel(float* __restrict__ C, const float* __restrict__ b) {
    const int row = blockIdx.x;
    float* Cp = C + (size_t)row * E_DIM;
    const int t = threadIdx.x;  // 0..127

    float4 v  = reinterpret_cast<float4*>(Cp)[t];
    float4 bb = reinterpret_cast<const float4*>(b)[t];
    v.x += bb.x; v.y += bb.y; v.z += bb.z; v.w += bb.w;

    float ss = v.x * v.x + v.y * v.y + v.z * v.z + v.w * v.w;
    #pragma unroll
    for (int o = 16; o > 0; o >>= 1) ss += __shfl_xor_sync(0xffffffff, ss, o);

    __shared__ float warpsum[4];
    if ((t & 31) == 0) warpsum[t >> 5] = ss;
    __syncthreads();
    const float tot = warpsum[0] + warpsum[1] + warpsum[2] + warpsum[3];
    const float scale = 1.0f / fmaxf(sqrtf(tot), 1e-12f);

    v.x *= scale; v.y *= scale; v.z *= scale; v.w *= scale;
    reinterpret_cast<float4*>(Cp)[t] = v;
}

// -----------------------------------------------------------------------------
extern "C" void kernel_launch(void* const* d_in, const int* in_sizes, int n_in,
                              void* d_out, int out_size) {
    const float* x = (const float*)d_in[0];   // (16384, 2048)
    const float* w = (const float*)d_in[1];   // (512, 1537)
    const float* b = (const float*)d_in[2];   // (512,)
    float* out = (float*)d_out;               // (16384, 512)

    cudaFuncSetAttribute(mma_gemm_kernel,
                         cudaFuncAttributeMaxDynamicSharedMemorySize, SMEM_BYTES);

    split_x_kernel<<<(N_ROWS * D_DIM) / (256 * 8), 256>>>(x);
    build_band_kernel<<<E_DIM, 256>>>(w);

    dim3 grid(E_DIM / BN, N_ROWS / BM);       // (4, 128)
    mma_gemm_kernel<<<grid, THREADS, SMEM_BYTES>>>(out);

    bias_normalize_kernel<<<N_ROWS, 128>>>(out, b);
}

// round 4
// speedup vs baseline: 2.6878x; 1.0321x over previous
#include <cuda_runtime.h>
#include <cuda_bf16.h>
#include <cstdint>

// ConvEmbedding: out[n,i] = normalize_row( sum_k w[i,k]*x[n,i+k] + b[i] )
// C = X(16384x2048) @ W_band(512x2048)^T, bf16 3-term split via mma.sync (HMMA).

#define N_ROWS 16384
#define D_DIM  2048
#define E_DIM  512
#define K_DIM  1537

#define BM 128
#define BN 128
#define BK 32
#define PITCH 40                 // bf16 elems per smem row (80 B)
#define NITER 52                 // 1664 / 32, uniform for every E tile
#define THREADS 256

#define TILE_SMEM (BM * PITCH * 2)           // 10240 B per tile
#define STAGE_SMEM (4 * TILE_SMEM)           // Ahi, Alo, Bhi, Blo = 40960 B
#define SMEM_BYTES (2 * STAGE_SMEM)          // double buffered = 81920 B

// ---------------- scratch (device globals) ----------------------------------
__device__ __nv_bfloat16 g_Xhi[(size_t)N_ROWS * D_DIM];
__device__ __nv_bfloat16 g_Xlo[(size_t)N_ROWS * D_DIM];
__device__ __nv_bfloat16 g_Whi[(size_t)E_DIM * D_DIM];
__device__ __nv_bfloat16 g_Wlo[(size_t)E_DIM * D_DIM];

// ---------------- kernel 1: split X into bf16 hi/lo --------------------------
__global__ __launch_bounds__(256)
void split_x_kernel(const float* __restrict__ x) {
    size_t i = ((size_t)blockIdx.x * 256 + threadIdx.x) * 8;
    float4 a = *reinterpret_cast<const float4*>(x + i);
    float4 c = *reinterpret_cast<const float4*>(x + i + 4);
    float v[8] = {a.x, a.y, a.z, a.w, c.x, c.y, c.z, c.w};
    __nv_bfloat16 hi[8], lo[8];
    #pragma unroll
    for (int j = 0; j < 8; j++) {
        hi[j] = __float2bfloat16(v[j]);
        lo[j] = __float2bfloat16(v[j] - __bfloat162float(hi[j]));
    }
    *reinterpret_cast<uint4*>(&g_Xhi[i]) = *reinterpret_cast<uint4*>(hi);
    *reinterpret_cast<uint4*>(&g_Xlo[i]) = *reinterpret_cast<uint4*>(lo);
}

// ---------------- kernel 2: build banded W, split hi/lo ----------------------
__global__ void build_band_kernel(const float* __restrict__ w) {
    const int i = blockIdx.x;  // 0..511
    const float* wrow = w + (size_t)i * K_DIM;
    for (int c = threadIdx.x; c < D_DIM; c += blockDim.x) {
        const int k = c - i;
        const float val = (k >= 0 && k < K_DIM) ? wrow[k] : 0.0f;
        const __nv_bfloat16 hi = __float2bfloat16(val);
        g_Whi[(size_t)i * D_DIM + c] = hi;
        g_Wlo[(size_t)i * D_DIM + c] = __float2bfloat16(val - __bfloat162float(hi));
    }
}

// ---------------- mma helpers ------------------------------------------------
__device__ __forceinline__ void ldm_x4(uint32_t* r, uint32_t saddr) {
    asm volatile("ldmatrix.sync.aligned.m8n8.x4.shared.b16 {%0,%1,%2,%3}, [%4];"
                 : "=r"(r[0]), "=r"(r[1]), "=r"(r[2]), "=r"(r[3]) : "r"(saddr));
}
__device__ __forceinline__ void mma_bf16(float* d, const uint32_t* a, const uint32_t* b) {
    asm volatile(
        "mma.sync.aligned.m16n8k16.row.col.f32.bf16.bf16.f32 "
        "{%0,%1,%2,%3}, {%4,%5,%6,%7}, {%8,%9}, {%0,%1,%2,%3};"
        : "+f"(d[0]), "+f"(d[1]), "+f"(d[2]), "+f"(d[3])
        : "r"(a[0]), "r"(a[1]), "r"(a[2]), "r"(a[3]), "r"(b[0]), "r"(b[1]));
}
__device__ __forceinline__ void cp_async16(uint32_t saddr, const void* gaddr) {
    asm volatile("cp.async.cg.shared.global [%0], [%1], 16;" :: "r"(saddr), "l"(gaddr));
}

// ---------------- kernel 3: bf16-split GEMM ----------------------------------
// Warp layout: 2 warps along M (tile 64) x 4 warps along N (tile 32).
// Per k16: 12 ldmatrix.x4 (each operand loaded once), 48 MMAs, term order
// hi*hi -> hi*lo -> lo*hi keeps every fragment single-load.
__global__ __launch_bounds__(THREADS, 2)
void mma_gemm_kernel(float* __restrict__ C) {
    extern __shared__ __align__(128) char smem[];
    const uint32_t sb = (uint32_t)__cvta_generic_to_shared(smem);

    const int tid  = threadIdx.x;
    const int lane = tid & 31;
    const int wid  = tid >> 5;
    const int wm   = wid & 1;          // 2 warps along M: rows wm*64
    const int wn   = wid >> 1;         // 4 warps along N: cols wn*32
    const int bx = blockIdx.x;         // E tile (0..3)
    const int by = blockIdx.y;         // batch tile (0..127)
    const int i0 = bx * BN;
    const int kStart = i0;

    // loader sources (tile order: 0=Ahi 1=Alo 2=Bhi 3=Blo)
    const __nv_bfloat16* srcs[4] = {
        g_Xhi + (size_t)by * BM * D_DIM,
        g_Xlo + (size_t)by * BM * D_DIM,
        g_Whi + (size_t)i0 * D_DIM,
        g_Wlo + (size_t)i0 * D_DIM
    };

    // per-thread loader coords: iteration i handles tile i>>1
    int lrow[8], lcol[8];
    #pragma unroll
    for (int i = 0; i < 8; i++) {
        const int v = ((i & 1) << 8) + tid;   // 0..511 within tile
        lrow[i] = v >> 2;
        lcol[i] = (v & 3) * 8;
    }

    // fragment smem offsets (bytes, lane-dependent), relative to tile base
    // A: m16k16 ldmatrix addr = row (lane&15), col-halves by lane>>4
    const uint32_t aoff = ((uint32_t)((wm * 64 + (lane & 15)) * PITCH + (lane >> 4) * 8)) * 2;
    // B: 16n x 16k ldmatrix addr
    const uint32_t boff = ((uint32_t)((wn * 32 + (lane >> 4) * 8 + (lane & 7)) * PITCH
                                      + ((lane >> 3) & 1) * 8)) * 2;

    float acc[4][4][4];
    #pragma unroll
    for (int mt = 0; mt < 4; mt++)
        #pragma unroll
        for (int nt = 0; nt < 4; nt++)
            #pragma unroll
            for (int q = 0; q < 4; q++) acc[mt][nt][q] = 0.0f;

    // ---- prologue: load stage 0
    {
        const int k0 = kStart;
        #pragma unroll
        for (int i = 0; i < 8; i++) {
            const int t = i >> 1;
            cp_async16(sb + t * TILE_SMEM + (lrow[i] * PITCH + lcol[i]) * 2,
                       srcs[t] + (size_t)lrow[i] * D_DIM + k0 + lcol[i]);
        }
        asm volatile("cp.async.commit_group;" ::: "memory");
    }

    for (int it = 0; it < NITER; it++) {
        if (it + 1 < NITER) {
            const int k0 = kStart + (it + 1) * BK;
            const uint32_t stg = sb + ((it + 1) & 1) * STAGE_SMEM;
            #pragma unroll
            for (int i = 0; i < 8; i++) {
                const int t = i >> 1;
                cp_async16(stg + t * TILE_SMEM + (lrow[i] * PITCH + lcol[i]) * 2,
                           srcs[t] + (size_t)lrow[i] * D_DIM + k0 + lcol[i]);
            }
            asm volatile("cp.async.commit_group;" ::: "memory");
            asm volatile("cp.async.wait_group 1;" ::: "memory");
        } else {
            asm volatile("cp.async.wait_group 0;" ::: "memory");
        }
        __syncthreads();

        const uint32_t stg = sb + (it & 1) * STAGE_SMEM;
        const uint32_t sAhi = stg + 0 * TILE_SMEM + aoff;
        const uint32_t sAlo = stg + 1 * TILE_SMEM + aoff;
        const uint32_t sBhi = stg + 2 * TILE_SMEM + boff;
        const uint32_t sBlo = stg + 3 * TILE_SMEM + boff;

        #pragma unroll
        for (int k16 = 0; k16 < BK; k16 += 16) {
            const uint32_t ko = k16 * 2;  // byte offset in row
            uint32_t a[16], bhi[8], blo[8];

            // load b_hi (2 x ldmatrix.x4 = 4 n8-tiles)
            #pragma unroll
            for (int bt = 0; bt < 2; bt++)
                ldm_x4(&bhi[bt * 4], sBhi + (uint32_t)(bt * 16 * PITCH) * 2 + ko);
            // load b_lo early (hides LDSM latency behind term1 MMAs)
            #pragma unroll
            for (int bt = 0; bt < 2; bt++)
                ldm_x4(&blo[bt * 4], sBlo + (uint32_t)(bt * 16 * PITCH) * 2 + ko);
            // load a_hi (4 m16 tiles)
            #pragma unroll
            for (int mt = 0; mt < 4; mt++)
                ldm_x4(&a[mt * 4], sAhi + (uint32_t)(mt * 16 * PITCH) * 2 + ko);

            // term 1: a_hi * b_hi
            #pragma unroll
            for (int mt = 0; mt < 4; mt++)
                #pragma unroll
                for (int nt = 0; nt < 4; nt++)
                    mma_bf16(acc[mt][nt], &a[mt * 4], &bhi[nt * 2]);

            // term 2: a_hi * b_lo (a resident)
            #pragma unroll
            for (int mt = 0; mt < 4; mt++)
                #pragma unroll
                for (int nt = 0; nt < 4; nt++)
                    mma_bf16(acc[mt][nt], &a[mt * 4], &blo[nt * 2]);

            // term 3: a_lo * b_hi (b_hi resident, a overwritten once)
            #pragma unroll
            for (int mt = 0; mt < 4; mt++)
                ldm_x4(&a[mt * 4], sAlo + (uint32_t)(mt * 16 * PITCH) * 2 + ko);
            #pragma unroll
            for (int mt = 0; mt < 4; mt++)
                #pragma unroll
                for (int nt = 0; nt < 4; nt++)
                    mma_bf16(acc[mt][nt], &a[mt * 4], &bhi[nt * 2]);
        }
        __syncthreads();
    }

    // ---- epilogue: direct stores, C frag layout of m16n8
    const int g = lane >> 2;
    const int c = lane & 3;
    #pragma unroll
    for (int mt = 0; mt < 4; mt++) {
        const int row0 = by * BM + wm * 64 + mt * 16 + g;
        #pragma unroll
        for (int nt = 0; nt < 4; nt++) {
            const int col = i0 + wn * 32 + nt * 8 + c * 2;
            float* p0 = C + (size_t)row0 * E_DIM + col;
            float* p1 = C + (size_t)(row0 + 8) * E_DIM + col;
            *reinterpret_cast<float2*>(p0) = make_float2(acc[mt][nt][0], acc[mt][nt][1]);
            *reinterpret_cast<float2*>(p1) = make_float2(acc[mt][nt][2], acc[mt][nt][3]);
        }
    }
}

// ---------------- kernel 4: bias + L2 normalize ------------------------------
__global__ void bias_normalize_kernel(float* __restrict__ C, const float* __restrict__ b) {
    const int row = blockIdx.x;
    float* Cp = C + (size_t)row * E_DIM;
    const int t = threadIdx.x;  // 0..127

    float4 v  = reinterpret_cast<float4*>(Cp)[t];
    float4 bb = reinterpret_cast<const float4*>(b)[t];
    v.x += bb.x; v.y += bb.y; v.z += bb.z; v.w += bb.w;

    float ss = v.x * v.x + v.y * v.y + v.z * v.z + v.w * v.w;
    #pragma unroll
    for (int o = 16; o > 0; o >>= 1) ss += __shfl_xor_sync(0xffffffff, ss, o);

    __shared__ float warpsum[4];
    if ((t & 31) == 0) warpsum[t >> 5] = ss;
    __syncthreads();
    const float tot = warpsum[0] + warpsum[1] + warpsum[2] + warpsum[3];
    const float scale = 1.0f / fmaxf(sqrtf(tot), 1e-12f);

    v.x *= scale; v.y *= scale; v.z *= scale; v.w *= scale;
    reinterpret_cast<float4*>(Cp)[t] = v;
}

// -----------------------------------------------------------------------------
extern "C" void kernel_launch(void* const* d_in, const int* in_sizes, int n_in,
                              void* d_out, int out_size) {
    const float* x = (const float*)d_in[0];   // (16384, 2048)
    const float* w = (const float*)d_in[1];   // (512, 1537)
    const float* b = (const float*)d_in[2];   // (512,)
    float* out = (float*)d_out;               // (16384, 512)

    cudaFuncSetAttribute(mma_gemm_kernel,
                         cudaFuncAttributeMaxDynamicSharedMemorySize, SMEM_BYTES);

    split_x_kernel<<<(N_ROWS * D_DIM) / (256 * 8), 256>>>(x);
    build_band_kernel<<<E_DIM, 256>>>(w);

    dim3 grid(E_DIM / BN, N_ROWS / BM);       // (4, 128)
    mma_gemm_kernel<<<grid, THREADS, SMEM_BYTES>>>(out);

    bias_normalize_kernel<<<N_ROWS, 128>>>(out, b);
}

// round 5
// speedup vs baseline: 2.9021x; 1.0797x over previous
#include <cuda_runtime.h>
#include <cuda_bf16.h>
#include <cstdint>

// ConvEmbedding: out[n,i] = normalize_row( sum_k w[i,k]*x[n,i+k] + b[i] )
// C = X(16384x2048) @ W_band(512x2048)^T, bf16 3-term split via mma.sync.
// R5: fp32->bf16hi/lo split for X fused into the GEMM A-loader (split_x removed).

#define N_ROWS 16384
#define D_DIM  2048
#define E_DIM  512
#define K_DIM  1537

#define BM 128
#define BN 128
#define BK 32
#define PITCH 40                 // bf16 elems per smem row (80 B)
#define NITER 52                 // 1664 / 32, uniform for every E tile
#define THREADS 256

#define TILE_SMEM (BM * PITCH * 2)           // 10240 B per tile
#define STAGE_SMEM (4 * TILE_SMEM)           // Ahi, Alo, Bhi, Blo = 40960 B
#define SMEM_BYTES (2 * STAGE_SMEM)          // double buffered = 81920 B

// ---------------- scratch (device globals) ----------------------------------
__device__ __nv_bfloat16 g_Whi[(size_t)E_DIM * D_DIM];
__device__ __nv_bfloat16 g_Wlo[(size_t)E_DIM * D_DIM];

// ---------------- kernel 1: build banded W, split hi/lo ----------------------
__global__ void build_band_kernel(const float* __restrict__ w) {
    const int i = blockIdx.x;  // 0..511
    const float* wrow = w + (size_t)i * K_DIM;
    for (int c = threadIdx.x; c < D_DIM; c += blockDim.x) {
        const int k = c - i;
        const float val = (k >= 0 && k < K_DIM) ? wrow[k] : 0.0f;
        const __nv_bfloat16 hi = __float2bfloat16(val);
        g_Whi[(size_t)i * D_DIM + c] = hi;
        g_Wlo[(size_t)i * D_DIM + c] = __float2bfloat16(val - __bfloat162float(hi));
    }
}

// ---------------- mma helpers ------------------------------------------------
__device__ __forceinline__ void ldm_x4(uint32_t* r, uint32_t saddr) {
    asm volatile("ldmatrix.sync.aligned.m8n8.x4.shared.b16 {%0,%1,%2,%3}, [%4];"
                 : "=r"(r[0]), "=r"(r[1]), "=r"(r[2]), "=r"(r[3]) : "r"(saddr));
}
__device__ __forceinline__ void mma_bf16(float* d, const uint32_t* a, const uint32_t* b) {
    asm volatile(
        "mma.sync.aligned.m16n8k16.row.col.f32.bf16.bf16.f32 "
        "{%0,%1,%2,%3}, {%4,%5,%6,%7}, {%8,%9}, {%0,%1,%2,%3};"
        : "+f"(d[0]), "+f"(d[1]), "+f"(d[2]), "+f"(d[3])
        : "r"(a[0]), "r"(a[1]), "r"(a[2]), "r"(a[3]), "r"(b[0]), "r"(b[1]));
}
__device__ __forceinline__ void cp_async16(uint32_t saddr, const void* gaddr) {
    asm volatile("cp.async.cg.shared.global [%0], [%1], 16;" :: "r"(saddr), "l"(gaddr));
}

// Convert 8 fp32 -> packed hi (4 u32) and lo (4 u32)
__device__ __forceinline__ void split8(const float* v, uint32_t* hi, uint32_t* lo) {
    #pragma unroll
    for (int j = 0; j < 4; j++) {
        const float a = v[j * 2], b = v[j * 2 + 1];
        const __nv_bfloat162 h = __float22bfloat162_rn(make_float2(a, b));
        const float ra = a - __bfloat162float(h.x);
        const float rb = b - __bfloat162float(h.y);
        const __nv_bfloat162 l = __float22bfloat162_rn(make_float2(ra, rb));
        hi[j] = *reinterpret_cast<const uint32_t*>(&h);
        lo[j] = *reinterpret_cast<const uint32_t*>(&l);
    }
}

// ---------------- kernel 2: bf16-split GEMM ----------------------------------
// Warp layout: 2 warps along M (tile 64) x 4 warps along N (tile 32).
// A loaded as fp32 LDG (one stage ahead), split to bf16 hi/lo in regs, STS'd.
__global__ __launch_bounds__(THREADS, 2)
void mma_gemm_kernel(const float* __restrict__ X, float* __restrict__ C) {
    extern __shared__ __align__(128) char smem[];
    const uint32_t sb = (uint32_t)__cvta_generic_to_shared(smem);

    const int tid  = threadIdx.x;
    const int lane = tid & 31;
    const int wid  = tid >> 5;
    const int wm   = wid & 1;          // 2 warps along M: rows wm*64
    const int wn   = wid >> 1;         // 4 warps along N: cols wn*32
    const int bx = blockIdx.x;         // E tile (0..3)
    const int by = blockIdx.y;         // batch tile (0..127)
    const int i0 = bx * BN;
    const int kStart = i0;

    // ---- A loader: thread handles row tid>>1, 16 consecutive cols
    const int arow = tid >> 1;
    const int acol = (tid & 1) * 16;
    const float* Ap = X + (size_t)(by * BM + arow) * D_DIM + acol;
    const uint32_t aSts = (uint32_t)(arow * PITCH + acol) * 2;  // byte off in tile

    // ---- B loader (cp.async): 4 chunks, tiles 2=Bhi 3=Blo at slots 2,3
    const __nv_bfloat16* Bsrc[2] = { g_Whi + (size_t)i0 * D_DIM,
                                     g_Wlo + (size_t)i0 * D_DIM };
    int brow[4], bcol[4];
    #pragma unroll
    for (int i = 0; i < 4; i++) {
        const int v = ((i & 1) << 8) + tid;   // 0..511 within tile
        brow[i] = v >> 2;
        bcol[i] = (v & 3) * 8;
    }

    // fragment smem offsets (bytes, lane-dependent), relative to tile base
    const uint32_t aoff = ((uint32_t)((wm * 64 + (lane & 15)) * PITCH + (lane >> 4) * 8)) * 2;
    const uint32_t boff = ((uint32_t)((wn * 32 + (lane >> 4) * 8 + (lane & 7)) * PITCH
                                      + ((lane >> 3) & 1) * 8)) * 2;

    float acc[4][4][4];
    #pragma unroll
    for (int mt = 0; mt < 4; mt++)
        #pragma unroll
        for (int nt = 0; nt < 4; nt++)
            #pragma unroll
            for (int q = 0; q < 4; q++) acc[mt][nt][q] = 0.0f;

    float av[16];   // fp32 A prefetch (one stage ahead)

    // ---- prologue: stage 0
    {
        const int k0 = kStart;
        #pragma unroll
        for (int i = 0; i < 4; i++)
            cp_async16(sb + (2 + (i >> 1)) * TILE_SMEM + (brow[i] * PITCH + bcol[i]) * 2,
                       Bsrc[i >> 1] + (size_t)brow[i] * D_DIM + k0 + bcol[i]);
        asm volatile("cp.async.commit_group;" ::: "memory");

        #pragma unroll
        for (int q = 0; q < 4; q++)
            *reinterpret_cast<float4*>(&av[q * 4]) =
                *reinterpret_cast<const float4*>(Ap + k0 + q * 4);
        uint32_t hi[8], lo[8];
        split8(&av[0], &hi[0], &lo[0]);
        split8(&av[8], &hi[4], &lo[4]);
        *reinterpret_cast<uint4*>(smem + 0 * TILE_SMEM + aSts)      = *reinterpret_cast<uint4*>(&hi[0]);
        *reinterpret_cast<uint4*>(smem + 0 * TILE_SMEM + aSts + 16) = *reinterpret_cast<uint4*>(&hi[4]);
        *reinterpret_cast<uint4*>(smem + 1 * TILE_SMEM + aSts)      = *reinterpret_cast<uint4*>(&lo[0]);
        *reinterpret_cast<uint4*>(smem + 1 * TILE_SMEM + aSts + 16) = *reinterpret_cast<uint4*>(&lo[4]);
    }

    for (int it = 0; it < NITER; it++) {
        const int has_next = (it + 1 < NITER);
        if (has_next) {
            const int k0 = kStart + (it + 1) * BK;
            const uint32_t stg = sb + ((it + 1) & 1) * STAGE_SMEM;
            #pragma unroll
            for (int i = 0; i < 4; i++)
                cp_async16(stg + (2 + (i >> 1)) * TILE_SMEM + (brow[i] * PITCH + bcol[i]) * 2,
                           Bsrc[i >> 1] + (size_t)brow[i] * D_DIM + k0 + bcol[i]);
            asm volatile("cp.async.commit_group;" ::: "memory");
            #pragma unroll
            for (int q = 0; q < 4; q++)
                *reinterpret_cast<float4*>(&av[q * 4]) =
                    *reinterpret_cast<const float4*>(Ap + k0 + q * 4);
            asm volatile("cp.async.wait_group 1;" ::: "memory");
        } else {
            asm volatile("cp.async.wait_group 0;" ::: "memory");
        }
        __syncthreads();

        const uint32_t stg = sb + (it & 1) * STAGE_SMEM;
        const uint32_t sAhi = stg + 0 * TILE_SMEM + aoff;
        const uint32_t sAlo = stg + 1 * TILE_SMEM + aoff;
        const uint32_t sBhi = stg + 2 * TILE_SMEM + boff;
        const uint32_t sBlo = stg + 3 * TILE_SMEM + boff;

        #pragma unroll
        for (int k16 = 0; k16 < BK; k16 += 16) {
            const uint32_t ko = k16 * 2;  // byte offset in row
            uint32_t a[16], bhi[8], blo[8];

            #pragma unroll
            for (int bt = 0; bt < 2; bt++)
                ldm_x4(&bhi[bt * 4], sBhi + (uint32_t)(bt * 16 * PITCH) * 2 + ko);
            #pragma unroll
            for (int bt = 0; bt < 2; bt++)
                ldm_x4(&blo[bt * 4], sBlo + (uint32_t)(bt * 16 * PITCH) * 2 + ko);
            #pragma unroll
            for (int mt = 0; mt < 4; mt++)
                ldm_x4(&a[mt * 4], sAhi + (uint32_t)(mt * 16 * PITCH) * 2 + ko);

            // term 1: a_hi * b_hi
            #pragma unroll
            for (int mt = 0; mt < 4; mt++)
                #pragma unroll
                for (int nt = 0; nt < 4; nt++)
                    mma_bf16(acc[mt][nt], &a[mt * 4], &bhi[nt * 2]);
            // term 2: a_hi * b_lo
            #pragma unroll
            for (int mt = 0; mt < 4; mt++)
                #pragma unroll
                for (int nt = 0; nt < 4; nt++)
                    mma_bf16(acc[mt][nt], &a[mt * 4], &blo[nt * 2]);
            // term 3: a_lo * b_hi
            #pragma unroll
            for (int mt = 0; mt < 4; mt++)
                ldm_x4(&a[mt * 4], sAlo + (uint32_t)(mt * 16 * PITCH) * 2 + ko);
            #pragma unroll
            for (int mt = 0; mt < 4; mt++)
                #pragma unroll
                for (int nt = 0; nt < 4; nt++)
                    mma_bf16(acc[mt][nt], &a[mt * 4], &bhi[nt * 2]);
        }
        __syncthreads();

        if (has_next) {
            char* stgN = smem + ((it + 1) & 1) * STAGE_SMEM;
            uint32_t hi[8], lo[8];
            split8(&av[0], &hi[0], &lo[0]);
            split8(&av[8], &hi[4], &lo[4]);
            *reinterpret_cast<uint4*>(stgN + 0 * TILE_SMEM + aSts)      = *reinterpret_cast<uint4*>(&hi[0]);
            *reinterpret_cast<uint4*>(stgN + 0 * TILE_SMEM + aSts + 16) = *reinterpret_cast<uint4*>(&hi[4]);
            *reinterpret_cast<uint4*>(stgN + 1 * TILE_SMEM + aSts)      = *reinterpret_cast<uint4*>(&lo[0]);
            *reinterpret_cast<uint4*>(stgN + 1 * TILE_SMEM + aSts + 16) = *reinterpret_cast<uint4*>(&lo[4]);
        }
    }

    // ---- epilogue: direct stores, C frag layout of m16n8
    const int g = lane >> 2;
    const int c = lane & 3;
    #pragma unroll
    for (int mt = 0; mt < 4; mt++) {
        const int row0 = by * BM + wm * 64 + mt * 16 + g;
        #pragma unroll
        for (int nt = 0; nt < 4; nt++) {
            const int col = i0 + wn * 32 + nt * 8 + c * 2;
            float* p0 = C + (size_t)row0 * E_DIM + col;
            float* p1 = C + (size_t)(row0 + 8) * E_DIM + col;
            *reinterpret_cast<float2*>(p0) = make_float2(acc[mt][nt][0], acc[mt][nt][1]);
            *reinterpret_cast<float2*>(p1) = make_float2(acc[mt][nt][2], acc[mt][nt][3]);
        }
    }
}

// ---------------- kernel 3: bias + L2 normalize ------------------------------
__global__ void bias_normalize_kernel(float* __restrict__ C, const float* __restrict__ b) {
    const int row = blockIdx.x;
    float* Cp = C + (size_t)row * E_DIM;
    const int t = threadIdx.x;  // 0..127

    float4 v  = reinterpret_cast<float4*>(Cp)[t];
    float4 bb = reinterpret_cast<const float4*>(b)[t];
    v.x += bb.x; v.y += bb.y; v.z += bb.z; v.w += bb.w;

    float ss = v.x * v.x + v.y * v.y + v.z * v.z + v.w * v.w;
    #pragma unroll
    for (int o = 16; o > 0; o >>= 1) ss += __shfl_xor_sync(0xffffffff, ss, o);

    __shared__ float warpsum[4];
    if ((t & 31) == 0) warpsum[t >> 5] = ss;
    __syncthreads();
    const float tot = warpsum[0] + warpsum[1] + warpsum[2] + warpsum[3];
    const float scale = 1.0f / fmaxf(sqrtf(tot), 1e-12f);

    v.x *= scale; v.y *= scale; v.z *= scale; v.w *= scale;
    reinterpret_cast<float4*>(Cp)[t] = v;
}

// -----------------------------------------------------------------------------
extern "C" void kernel_launch(void* const* d_in, const int* in_sizes, int n_in,
                              void* d_out, int out_size) {
    const float* x = (const float*)d_in[0];   // (16384, 2048)
    const float* w = (const float*)d_in[1];   // (512, 1537)
    const float* b = (const float*)d_in[2];   // (512,)
    float* out = (float*)d_out;               // (16384, 512)

    cudaFuncSetAttribute(mma_gemm_kernel,
                         cudaFuncAttributeMaxDynamicSharedMemorySize, SMEM_BYTES);

    build_band_kernel<<<E_DIM, 256>>>(w);

    dim3 grid(E_DIM / BN, N_ROWS / BM);       // (4, 128)
    mma_gemm_kernel<<<grid, THREADS, SMEM_BYTES>>>(x, out);

    bias_normalize_kernel<<<N_ROWS, 128>>>(out, b);
}